// round 7
// baseline (speedup 1.0000x reference)
#include <cuda_runtime.h>
#include <math.h>

#define Hdim 384
#define Wdim 384
#define HWp  (Hdim*Wdim)
#define BATCH 8
#define PER_IMG (2*Wdim + 2*(Hdim-2))   // 1532 border pixels per image
#define NBORD  (BATCH*PER_IMG)

// Cox-de Boor cubic bases (exact recursion; border kernel only)
__device__ __forceinline__ void spline_bases(float v, float* b8)
{
    float b[11];
#pragma unroll
    for (int i = 0; i < 11; i++) {
        float gi  = (i - 3) * 0.4f - 1.0f;
        float gi1 = (i - 2) * 0.4f - 1.0f;
        b[i] = (v >= gi && v < gi1) ? 1.f : 0.f;
    }
#pragma unroll
    for (int k = 1; k <= 3; k++) {
        float rinv = 1.0f / (0.4f * (float)k);
#pragma unroll
        for (int i = 0; i + k < 11; i++) {
            float gi   = (i - 3) * 0.4f - 1.0f;
            float gik1 = (i + k - 2) * 0.4f - 1.0f;
            b[i] = (v - gi) * rinv * b[i] + (gik1 - v) * rinv * b[i + 1];
        }
    }
#pragma unroll
    for (int m = 0; m < 8; m++) b8[m] = b[m];
}

// Build G[c][di][dj][m] into smem (1296 floats) from the raw params.
__device__ __forceinline__ void build_G(float* sG, int t, int nthr,
                                        const float* __restrict__ bw,
                                        const float* __restrict__ sw,
                                        const float* __restrict__ ss)
{
    for (int idx = t; idx < 16 * 81; idx += nthr) {
        int c = idx / 81, r = idx % 81;
        int di = r / 27, dj = (r / 9) % 3, m = r % 9;
        int k = di * 3 + dj;
        float val;
        if (m == 0) val = bw[c * 9 + k];
        else        val = sw[(c * 9 + k) * 8 + (m - 1)] * ss[c * 9 + k];
        sG[((c * 3 + di) * 3 + dj) * 9 + m] = val;
    }
}

// One composed weight H[cls][m][du*5+dv] from smem G + rw.
__device__ __forceinline__ float compose_H(const float* sG, const float* srw,
                                           int ri, int rj, int m, int du, int dv)
{
    float s0 = 0.f, s1 = 0.f;
    for (int u = 0; u < 3; u++) {
        if (ri == 0 && u == 0) continue;
        if (ri == 2 && u == 2) continue;
        int di = du - u; if (di < 0 || di > 2) continue;
        for (int v = 0; v < 3; v++) {
            if (rj == 0 && v == 0) continue;
            if (rj == 2 && v == 2) continue;
            int dj = dv - v; if (dj < 0 || dj > 2) continue;
#pragma unroll
            for (int c = 0; c < 16; c += 2) {
                s0 = fmaf(srw[(c * 3 + u) * 3 + v],
                          sG[((c * 3 + di) * 3 + dj) * 9 + m], s0);
                s1 = fmaf(srw[((c + 1) * 3 + u) * 3 + v],
                          sG[(((c + 1) * 3 + di) * 3 + dj) * 9 + m], s1);
            }
        }
    }
    return s0 + s1;
}

// ---------------------------------------------------------------------------
// Kernel 1: self-contained fused kernel: per-block H composition (interior
// class), on-the-fly features, composed 5x5 conv. 128 threads, 2x4 micro-
// tile, 32x32 block tile, 36x36 halo.
// ---------------------------------------------------------------------------
__global__ void __launch_bounds__(128) main_kernel(const float* __restrict__ x,
                                                   float* __restrict__ out,
                                                   const float* __restrict__ rb,
                                                   const float* __restrict__ bw,
                                                   const float* __restrict__ sw,
                                                   const float* __restrict__ ss,
                                                   const float* __restrict__ rw)
{
    __shared__ union SmemU {
        float sF[9][36 * 36];                     // feature planes (stage B)
        struct { float G[16 * 81]; float rw_[144]; } pre;   // stage A scratch
    } S;
    __shared__ float sH[225];

    int t  = threadIdx.x;
    int tx = t & 7, ty = t >> 3;        // 8 x 16 threads
    int gx0 = blockIdx.x * 32, gy0 = blockIdx.y * 32;
    int bz = blockIdx.z;

    // --- Stage A: compose interior H in smem ---
    for (int i = t; i < 144; i += 128) S.pre.rw_[i] = rw[i];   // FIX: strided
    build_G(S.pre.G, t, 128, bw, sw, ss);
    __syncthreads();
    for (int idx = t; idx < 225; idx += 128) {
        int m = idx / 25, r = idx % 25;
        sH[idx] = compose_H(S.pre.G, S.pre.rw_, 1, 1, m, r / 5, r % 5);
    }
    __syncthreads();   // G no longer needed; sF may be written now

    // --- Stage B: features of the 36x36 halo tile ---
    const float* xp = x + (size_t)bz * HWp;
    for (int idx = t; idx < 36 * 36; idx += 128) {
        int r = idx / 36, c2 = idx - r * 36;
        int gy = gy0 - 2 + r, gx = gx0 - 2 + c2;
        float v = 0.f;
        if (gy >= 0 && gy < Hdim && gx >= 0 && gx < Wdim)
            v = __ldg(&xp[gy * Wdim + gx]);

        float sig = 1.0f / (1.0f + __expf(-v));
        S.sF[0][idx] = v * sig;
#pragma unroll
        for (int m = 1; m < 9; m++) S.sF[m][idx] = 0.f;

        // interval index on knots g_i = 0.4*i - 2.2 (i = 0..11)
        float sc = (v + 2.2f) * 2.5f;
        float tf = floorf(sc);
        int   ti = (int)tf;
        if (ti >= 0 && ti <= 10) {
            float gt = tf * 0.4f - 2.2f;
            float u  = (v - gt) * 2.5f;
            float u1 = 1.0f - u;
            float u2 = u * u, u12 = u1 * u1;
            const float c6 = 1.0f / 6.0f;
            float w0 = u12 * u1 * c6;
            float w1 = (3.f*u2*u - 6.f*u2 + 4.f) * c6;
            float w2 = (-3.f*u2*u + 3.f*u2 + 3.f*u + 1.f) * c6;
            float w3 = u2 * u * c6;
            int m0 = ti - 3;
            if (m0     >= 0 && m0     <= 7) S.sF[m0 + 1][idx] = w0;
            if (m0 + 1 >= 0 && m0 + 1 <= 7) S.sF[m0 + 2][idx] = w1;
            if (m0 + 2 >= 0 && m0 + 2 <= 7) S.sF[m0 + 3][idx] = w2;
            if (ti     >= 0 && ti     <= 7) S.sF[ti + 1][idx] = w3;
        }
    }
    __syncthreads();

    // --- Stage C: scalar 5x5 conv over 9 planes, 2x4 outputs/thread ---
    float acc[2][4] = {};
#pragma unroll 1
    for (int m = 0; m < 9; m++) {
        float win[6][8];
#pragma unroll
        for (int dy = 0; dy < 6; dy++) {
            const float* row = &S.sF[m][(ty * 2 + dy) * 36 + tx * 4];
            float4 a  = *(const float4*)(row);
            float4 bq = *(const float4*)(row + 4);
            win[dy][0] = a.x;  win[dy][1] = a.y;  win[dy][2] = a.z;  win[dy][3] = a.w;
            win[dy][4] = bq.x; win[dy][5] = bq.y; win[dy][6] = bq.z; win[dy][7] = bq.w;
        }
        const float* Hm = &sH[m * 25];
#pragma unroll
        for (int du = 0; du < 5; du++)
#pragma unroll
            for (int dv = 0; dv < 5; dv++) {
                float h = Hm[du * 5 + dv];
#pragma unroll
                for (int ry = 0; ry < 2; ry++)
#pragma unroll
                    for (int rx = 0; rx < 4; rx++)
                        acc[ry][rx] = fmaf(h, win[ry + du][rx + dv], acc[ry][rx]);
            }
    }

    float rbv = __ldg(rb);
    float* op = out + (size_t)bz * HWp;
#pragma unroll
    for (int ry = 0; ry < 2; ry++) {
        int oy = gy0 + ty * 2 + ry;
        float4 o;
        o.x = acc[ry][0] + rbv; o.y = acc[ry][1] + rbv;
        o.z = acc[ry][2] + rbv; o.w = acc[ry][3] + rbv;
        *(float4*)&op[(size_t)oy * Wdim + gx0 + tx * 4] = o;
    }
}

// ---------------------------------------------------------------------------
// Kernel 2: border ring. Each block composes only the Hc classes present
// among its pixels (<=3), then evaluates its pixels from smem weights.
// ---------------------------------------------------------------------------
__global__ void __launch_bounds__(128) border_kernel(const float* __restrict__ x,
                                                     float* __restrict__ out,
                                                     const float* __restrict__ rb,
                                                     const float* __restrict__ bw,
                                                     const float* __restrict__ sw,
                                                     const float* __restrict__ ss,
                                                     const float* __restrict__ rw)
{
    __shared__ float sG[16 * 81];
    __shared__ float srw[144];
    __shared__ float sHc[9][225];
    __shared__ int clsmask;

    int t = threadIdx.x;
    int pix = blockIdx.x * 128 + t;
    bool valid = (pix < NBORD);

    int b = 0, i = 0, j = 0, cls = 0;
    if (valid) {
        b = pix / PER_IMG;
        int e = pix % PER_IMG;
        if (e < Wdim)            { i = 0;        j = e; }
        else if (e < 2 * Wdim)   { i = Hdim - 1; j = e - Wdim; }
        else if (e < 2 * Wdim + (Hdim - 2)) { i = e - 2 * Wdim + 1; j = 0; }
        else                     { i = e - (2 * Wdim + (Hdim - 2)) + 1; j = Wdim - 1; }
        int ri = (i == 0) ? 0 : ((i == Hdim - 1) ? 2 : 1);
        int rj = (j == 0) ? 0 : ((j == Wdim - 1) ? 2 : 1);
        cls = ri * 3 + rj;
    }

    if (t == 0) clsmask = 0;
    for (int i2 = t; i2 < 144; i2 += 128) srw[i2] = rw[i2];   // FIX: strided
    build_G(sG, t, 128, bw, sw, ss);
    __syncthreads();
    if (valid) atomicOr(&clsmask, 1 << cls);
    __syncthreads();

    int mask = clsmask;   // uniform across block
    for (int c2 = 0; c2 < 9; c2++) {
        if (!((mask >> c2) & 1)) continue;
        int ri = c2 / 3, rj = c2 % 3;
        for (int idx = t; idx < 225; idx += 128) {
            int m = idx / 25, r = idx % 25;
            sHc[c2][idx] = compose_H(sG, srw, ri, rj, m, r / 5, r % 5);
        }
    }
    __syncthreads();

    if (!valid) return;
    const float* Hc = sHc[cls];
    const float* xp = x + (size_t)b * HWp;

    float acc = 0.f;
#pragma unroll
    for (int du = 0; du < 5; du++) {
        int fy = i + du - 2;
#pragma unroll
        for (int dv = 0; dv < 5; dv++) {
            int fx = j + dv - 2;
            float v = 0.f;
            if (fy >= 0 && fy < Hdim && fx >= 0 && fx < Wdim)
                v = __ldg(&xp[fy * Wdim + fx]);
            float sig = 1.0f / (1.0f + __expf(-v));
            float f0 = v * sig;
            float b8[8];
            spline_bases(v, b8);
            int pos = du * 5 + dv;
            acc = fmaf(Hc[pos], f0, acc);
#pragma unroll
            for (int m = 0; m < 8; m++)
                acc = fmaf(Hc[(m + 1) * 25 + pos], b8[m], acc);
        }
    }
    out[(size_t)b * HWp + (size_t)i * Wdim + j] = acc + __ldg(rb);
}

// ---------------------------------------------------------------------------
extern "C" void kernel_launch(void* const* d_in, const int* in_sizes, int n_in,
                              void* d_out, int out_size)
{
    const float* x  = (const float*)d_in[0];
    const float* bw = (const float*)d_in[1];
    const float* sw = (const float*)d_in[2];
    const float* ss = (const float*)d_in[3];
    const float* rw = (const float*)d_in[4];
    const float* rb = (const float*)d_in[5];
    float* out = (float*)d_out;

    dim3 grid(Wdim / 32, Hdim / 32, BATCH);
    main_kernel<<<grid, 128>>>(x, out, rb, bw, sw, ss, rw);
    border_kernel<<<(NBORD + 127) / 128, 128>>>(x, out, rb, bw, sw, ss, rw);
}

// round 8
// speedup vs baseline: 1.1367x; 1.1367x over previous
#include <cuda_runtime.h>
#include <math.h>

#define Hdim 384
#define Wdim 384
#define HWp  (Hdim*Wdim)
#define BATCH 8
#define PER_IMG (2*Wdim + 2*(Hdim-2))   // 1532 border pixels per image
#define NBORD  (BATCH*PER_IMG)

// Composed per-border-class weights, written by main_kernel block (0,0,0),
// consumed by border_kernel (later launch on the same stream).
__device__ float g_Hc[9][225];

// Cox-de Boor cubic bases (exact recursion; border kernel only)
__device__ __forceinline__ void spline_bases(float v, float* b8)
{
    float b[11];
#pragma unroll
    for (int i = 0; i < 11; i++) {
        float gi  = (i - 3) * 0.4f - 1.0f;
        float gi1 = (i - 2) * 0.4f - 1.0f;
        b[i] = (v >= gi && v < gi1) ? 1.f : 0.f;
    }
#pragma unroll
    for (int k = 1; k <= 3; k++) {
        float rinv = 1.0f / (0.4f * (float)k);
#pragma unroll
        for (int i = 0; i + k < 11; i++) {
            float gi   = (i - 3) * 0.4f - 1.0f;
            float gik1 = (i + k - 2) * 0.4f - 1.0f;
            b[i] = (v - gi) * rinv * b[i] + (gik1 - v) * rinv * b[i + 1];
        }
    }
#pragma unroll
    for (int m = 0; m < 8; m++) b8[m] = b[m];
}

// Build G[c][di][dj][m] into smem (1296 floats) from the raw params.
__device__ __forceinline__ void build_G(float* sG, int t, int nthr,
                                        const float* __restrict__ bw,
                                        const float* __restrict__ sw,
                                        const float* __restrict__ ss)
{
    for (int idx = t; idx < 16 * 81; idx += nthr) {
        int c = idx / 81, r = idx % 81;
        int di = r / 27, dj = (r / 9) % 3, m = r % 9;
        int k = di * 3 + dj;
        float val;
        if (m == 0) val = bw[c * 9 + k];
        else        val = sw[(c * 9 + k) * 8 + (m - 1)] * ss[c * 9 + k];
        sG[((c * 3 + di) * 3 + dj) * 9 + m] = val;
    }
}

// One composed weight H[cls][m][du*5+dv] from smem G + rw.
__device__ __forceinline__ float compose_H(const float* sG, const float* srw,
                                           int ri, int rj, int m, int du, int dv)
{
    float s0 = 0.f, s1 = 0.f;
    for (int u = 0; u < 3; u++) {
        if (ri == 0 && u == 0) continue;
        if (ri == 2 && u == 2) continue;
        int di = du - u; if (di < 0 || di > 2) continue;
        for (int v = 0; v < 3; v++) {
            if (rj == 0 && v == 0) continue;
            if (rj == 2 && v == 2) continue;
            int dj = dv - v; if (dj < 0 || dj > 2) continue;
#pragma unroll
            for (int c = 0; c < 16; c += 2) {
                s0 = fmaf(srw[(c * 3 + u) * 3 + v],
                          sG[((c * 3 + di) * 3 + dj) * 9 + m], s0);
                s1 = fmaf(srw[((c + 1) * 3 + u) * 3 + v],
                          sG[(((c + 1) * 3 + di) * 3 + dj) * 9 + m], s1);
            }
        }
    }
    return s0 + s1;
}

// ---------------------------------------------------------------------------
// Kernel 1: fused: per-block interior-H composition, on-the-fly features,
// composed 5x5 conv. Block (0,0,0) additionally exports all 9 Hc classes to
// global for the border kernel. 128 threads, 2x4 micro-tile, 32x32 tile.
// ---------------------------------------------------------------------------
__global__ void __launch_bounds__(128) main_kernel(const float* __restrict__ x,
                                                   float* __restrict__ out,
                                                   const float* __restrict__ rb,
                                                   const float* __restrict__ bw,
                                                   const float* __restrict__ sw,
                                                   const float* __restrict__ ss,
                                                   const float* __restrict__ rw)
{
    __shared__ union SmemU {
        float sF[9][36 * 36];                                // stage B/C
        struct { float G[16 * 81]; float rw_[144]; } pre;    // stage A scratch
    } S;
    __shared__ float sH[225];

    int t  = threadIdx.x;
    int tx = t & 7, ty = t >> 3;        // 8 x 16 threads
    int gx0 = blockIdx.x * 32, gy0 = blockIdx.y * 32;
    int bz = blockIdx.z;

    // --- Stage A: compose interior H in smem ---
    for (int i = t; i < 144; i += 128) S.pre.rw_[i] = rw[i];
    build_G(S.pre.G, t, 128, bw, sw, ss);
    __syncthreads();
    for (int idx = t; idx < 225; idx += 128) {
        int m = idx / 25, r = idx % 25;
        sH[idx] = compose_H(S.pre.G, S.pre.rw_, 1, 1, m, r / 5, r % 5);
    }
    // Designated block exports all 9 classes for the border kernel.
    if (blockIdx.x == 0 && blockIdx.y == 0 && bz == 0) {
        for (int idx = t; idx < 9 * 225; idx += 128) {
            int cls = idx / 225, rem = idx % 225;
            int m = rem / 25, r = rem % 25;
            g_Hc[cls][rem] = compose_H(S.pre.G, S.pre.rw_,
                                       cls / 3, cls % 3, m, r / 5, r % 5);
        }
    }
    __syncthreads();   // G dead; sF may be written now

    // --- Stage B: features of the 36x36 halo tile ---
    const float* xp = x + (size_t)bz * HWp;
    for (int idx = t; idx < 36 * 36; idx += 128) {
        int r = idx / 36, c2 = idx - r * 36;
        int gy = gy0 - 2 + r, gx = gx0 - 2 + c2;
        float v = 0.f;
        if (gy >= 0 && gy < Hdim && gx >= 0 && gx < Wdim)
            v = __ldg(&xp[gy * Wdim + gx]);

        float sig = 1.0f / (1.0f + __expf(-v));
        S.sF[0][idx] = v * sig;
#pragma unroll
        for (int m = 1; m < 9; m++) S.sF[m][idx] = 0.f;

        float sc = (v + 2.2f) * 2.5f;
        float tf = floorf(sc);
        int   ti = (int)tf;
        if (ti >= 0 && ti <= 10) {
            float gt = tf * 0.4f - 2.2f;
            float u  = (v - gt) * 2.5f;
            float u1 = 1.0f - u;
            float u2 = u * u, u12 = u1 * u1;
            const float c6 = 1.0f / 6.0f;
            float w0 = u12 * u1 * c6;
            float w1 = (3.f*u2*u - 6.f*u2 + 4.f) * c6;
            float w2 = (-3.f*u2*u + 3.f*u2 + 3.f*u + 1.f) * c6;
            float w3 = u2 * u * c6;
            int m0 = ti - 3;
            if (m0     >= 0 && m0     <= 7) S.sF[m0 + 1][idx] = w0;
            if (m0 + 1 >= 0 && m0 + 1 <= 7) S.sF[m0 + 2][idx] = w1;
            if (m0 + 2 >= 0 && m0 + 2 <= 7) S.sF[m0 + 3][idx] = w2;
            if (ti     >= 0 && ti     <= 7) S.sF[ti + 1][idx] = w3;
        }
    }
    __syncthreads();

    // --- Stage C: scalar 5x5 conv over 9 planes, 2x4 outputs/thread ---
    float acc[2][4] = {};
#pragma unroll 1
    for (int m = 0; m < 9; m++) {
        float win[6][8];
#pragma unroll
        for (int dy = 0; dy < 6; dy++) {
            const float* row = &S.sF[m][(ty * 2 + dy) * 36 + tx * 4];
            float4 a  = *(const float4*)(row);
            float4 bq = *(const float4*)(row + 4);
            win[dy][0] = a.x;  win[dy][1] = a.y;  win[dy][2] = a.z;  win[dy][3] = a.w;
            win[dy][4] = bq.x; win[dy][5] = bq.y; win[dy][6] = bq.z; win[dy][7] = bq.w;
        }
        const float* Hm = &sH[m * 25];
#pragma unroll
        for (int du = 0; du < 5; du++)
#pragma unroll
            for (int dv = 0; dv < 5; dv++) {
                float h = Hm[du * 5 + dv];
#pragma unroll
                for (int ry = 0; ry < 2; ry++)
#pragma unroll
                    for (int rx = 0; rx < 4; rx++)
                        acc[ry][rx] = fmaf(h, win[ry + du][rx + dv], acc[ry][rx]);
            }
    }

    float rbv = __ldg(rb);
    float* op = out + (size_t)bz * HWp;
#pragma unroll
    for (int ry = 0; ry < 2; ry++) {
        int oy = gy0 + ty * 2 + ry;
        float4 o;
        o.x = acc[ry][0] + rbv; o.y = acc[ry][1] + rbv;
        o.z = acc[ry][2] + rbv; o.w = acc[ry][3] + rbv;
        *(float4*)&op[(size_t)oy * Wdim + gx0 + tx * 4] = o;
    }
}

// ---------------------------------------------------------------------------
// Kernel 2: border ring, one thread per pixel, reads precomposed g_Hc from
// global (8KB, L2-resident). Features on the fly from the 5x5 neighborhood.
// ---------------------------------------------------------------------------
__global__ void border_kernel(const float* __restrict__ x,
                              float* __restrict__ out,
                              const float* __restrict__ rb)
{
    int pix = blockIdx.x * blockDim.x + threadIdx.x;
    if (pix >= NBORD) return;
    int b = pix / PER_IMG, e = pix % PER_IMG;
    int i, j;
    if (e < Wdim)            { i = 0;        j = e; }
    else if (e < 2 * Wdim)   { i = Hdim - 1; j = e - Wdim; }
    else if (e < 2 * Wdim + (Hdim - 2)) { i = e - 2 * Wdim + 1; j = 0; }
    else                     { i = e - (2 * Wdim + (Hdim - 2)) + 1; j = Wdim - 1; }

    int ri = (i == 0) ? 0 : ((i == Hdim - 1) ? 2 : 1);
    int rj = (j == 0) ? 0 : ((j == Wdim - 1) ? 2 : 1);
    const float* Hc = g_Hc[ri * 3 + rj];
    const float* xp = x + (size_t)b * HWp;

    float acc = 0.f;
#pragma unroll
    for (int du = 0; du < 5; du++) {
        int fy = i + du - 2;
#pragma unroll
        for (int dv = 0; dv < 5; dv++) {
            int fx = j + dv - 2;
            float v = 0.f;
            if (fy >= 0 && fy < Hdim && fx >= 0 && fx < Wdim)
                v = __ldg(&xp[fy * Wdim + fx]);
            float sig = 1.0f / (1.0f + __expf(-v));
            float f0 = v * sig;
            float b8[8];
            spline_bases(v, b8);
            int pos = du * 5 + dv;
            acc = fmaf(__ldg(&Hc[pos]), f0, acc);
#pragma unroll
            for (int m = 0; m < 8; m++)
                acc = fmaf(__ldg(&Hc[(m + 1) * 25 + pos]), b8[m], acc);
        }
    }
    out[(size_t)b * HWp + (size_t)i * Wdim + j] = acc + __ldg(rb);
}

// ---------------------------------------------------------------------------
extern "C" void kernel_launch(void* const* d_in, const int* in_sizes, int n_in,
                              void* d_out, int out_size)
{
    const float* x  = (const float*)d_in[0];
    const float* bw = (const float*)d_in[1];
    const float* sw = (const float*)d_in[2];
    const float* ss = (const float*)d_in[3];
    const float* rw = (const float*)d_in[4];
    const float* rb = (const float*)d_in[5];
    float* out = (float*)d_out;

    dim3 grid(Wdim / 32, Hdim / 32, BATCH);
    main_kernel<<<grid, 128>>>(x, out, rb, bw, sw, ss, rw);
    border_kernel<<<(NBORD + 127) / 128, 128>>>(x, out, rb);
}

// round 9
// speedup vs baseline: 1.3647x; 1.2006x over previous
#include <cuda_runtime.h>
#include <math.h>

#define Hdim 384
#define Wdim 384
#define HWp  (Hdim*Wdim)
#define BATCH 8
#define PER_IMG (2*Wdim + 2*(Hdim-2))   // 1532 border pixels per image
#define NBORD  (BATCH*PER_IMG)

// Composed per-border-class weights, written by main_kernel block (0,0,0),
// consumed by border_kernel (later launch on the same stream).
__device__ float g_Hc[9][225];

// Build G[c][di][dj][m] into smem (1296 floats) from the raw params.
__device__ __forceinline__ void build_G(float* sG, int t, int nthr,
                                        const float* __restrict__ bw,
                                        const float* __restrict__ sw,
                                        const float* __restrict__ ss)
{
    for (int idx = t; idx < 16 * 81; idx += nthr) {
        int c = idx / 81, r = idx % 81;
        int di = r / 27, dj = (r / 9) % 3, m = r % 9;
        int k = di * 3 + dj;
        float val;
        if (m == 0) val = bw[c * 9 + k];
        else        val = sw[(c * 9 + k) * 8 + (m - 1)] * ss[c * 9 + k];
        sG[((c * 3 + di) * 3 + dj) * 9 + m] = val;
    }
}

// One composed weight H[cls][m][du*5+dv] from smem G + rw.
__device__ __forceinline__ float compose_H(const float* sG, const float* srw,
                                           int ri, int rj, int m, int du, int dv)
{
    float s0 = 0.f, s1 = 0.f;
    for (int u = 0; u < 3; u++) {
        if (ri == 0 && u == 0) continue;
        if (ri == 2 && u == 2) continue;
        int di = du - u; if (di < 0 || di > 2) continue;
        for (int v = 0; v < 3; v++) {
            if (rj == 0 && v == 0) continue;
            if (rj == 2 && v == 2) continue;
            int dj = dv - v; if (dj < 0 || dj > 2) continue;
#pragma unroll
            for (int c = 0; c < 16; c += 2) {
                s0 = fmaf(srw[(c * 3 + u) * 3 + v],
                          sG[((c * 3 + di) * 3 + dj) * 9 + m], s0);
                s1 = fmaf(srw[((c + 1) * 3 + u) * 3 + v],
                          sG[(((c + 1) * 3 + di) * 3 + dj) * 9 + m], s1);
            }
        }
    }
    return s0 + s1;
}

// ---------------------------------------------------------------------------
// Kernel 1: fused: per-block interior-H composition, on-the-fly features,
// composed 5x5 conv. Block (0,0,0) additionally exports all 9 Hc classes to
// global for the border kernel. 128 threads, 2x4 micro-tile, 32x32 tile.
// ---------------------------------------------------------------------------
__global__ void __launch_bounds__(128) main_kernel(const float* __restrict__ x,
                                                   float* __restrict__ out,
                                                   const float* __restrict__ rb,
                                                   const float* __restrict__ bw,
                                                   const float* __restrict__ sw,
                                                   const float* __restrict__ ss,
                                                   const float* __restrict__ rw)
{
    __shared__ union SmemU {
        float sF[9][36 * 36];                                // stage B/C
        struct { float G[16 * 81]; float rw_[144]; } pre;    // stage A scratch
    } S;
    __shared__ float sH[225];

    int t  = threadIdx.x;
    int tx = t & 7, ty = t >> 3;        // 8 x 16 threads
    int gx0 = blockIdx.x * 32, gy0 = blockIdx.y * 32;
    int bz = blockIdx.z;

    // --- Stage A: compose interior H in smem ---
    for (int i = t; i < 144; i += 128) S.pre.rw_[i] = rw[i];
    build_G(S.pre.G, t, 128, bw, sw, ss);
    __syncthreads();
    for (int idx = t; idx < 225; idx += 128) {
        int m = idx / 25, r = idx % 25;
        sH[idx] = compose_H(S.pre.G, S.pre.rw_, 1, 1, m, r / 5, r % 5);
    }
    // Designated block exports all 9 classes for the border kernel.
    if (blockIdx.x == 0 && blockIdx.y == 0 && bz == 0) {
        for (int idx = t; idx < 9 * 225; idx += 128) {
            int cls = idx / 225, rem = idx % 225;
            int m = rem / 25, r = rem % 25;
            g_Hc[cls][rem] = compose_H(S.pre.G, S.pre.rw_,
                                       cls / 3, cls % 3, m, r / 5, r % 5);
        }
    }
    __syncthreads();   // G dead; sF may be written now

    // --- Stage B: features of the 36x36 halo tile ---
    const float* xp = x + (size_t)bz * HWp;
    for (int idx = t; idx < 36 * 36; idx += 128) {
        int r = idx / 36, c2 = idx - r * 36;
        int gy = gy0 - 2 + r, gx = gx0 - 2 + c2;
        float v = 0.f;
        if (gy >= 0 && gy < Hdim && gx >= 0 && gx < Wdim)
            v = __ldg(&xp[gy * Wdim + gx]);

        float sig = 1.0f / (1.0f + __expf(-v));
        S.sF[0][idx] = v * sig;
#pragma unroll
        for (int m = 1; m < 9; m++) S.sF[m][idx] = 0.f;

        float sc = (v + 2.2f) * 2.5f;
        float tf = floorf(sc);
        int   ti = (int)tf;
        if (ti >= 0 && ti <= 10) {
            float gt = tf * 0.4f - 2.2f;
            float u  = (v - gt) * 2.5f;
            float u1 = 1.0f - u;
            float u2 = u * u, u12 = u1 * u1;
            const float c6 = 1.0f / 6.0f;
            float w0 = u12 * u1 * c6;
            float w1 = (3.f*u2*u - 6.f*u2 + 4.f) * c6;
            float w2 = (-3.f*u2*u + 3.f*u2 + 3.f*u + 1.f) * c6;
            float w3 = u2 * u * c6;
            int m0 = ti - 3;
            if (m0     >= 0 && m0     <= 7) S.sF[m0 + 1][idx] = w0;
            if (m0 + 1 >= 0 && m0 + 1 <= 7) S.sF[m0 + 2][idx] = w1;
            if (m0 + 2 >= 0 && m0 + 2 <= 7) S.sF[m0 + 3][idx] = w2;
            if (ti     >= 0 && ti     <= 7) S.sF[ti + 1][idx] = w3;
        }
    }
    __syncthreads();

    // --- Stage C: scalar 5x5 conv over 9 planes, 2x4 outputs/thread ---
    float acc[2][4] = {};
#pragma unroll 1
    for (int m = 0; m < 9; m++) {
        float win[6][8];
#pragma unroll
        for (int dy = 0; dy < 6; dy++) {
            const float* row = &S.sF[m][(ty * 2 + dy) * 36 + tx * 4];
            float4 a  = *(const float4*)(row);
            float4 bq = *(const float4*)(row + 4);
            win[dy][0] = a.x;  win[dy][1] = a.y;  win[dy][2] = a.z;  win[dy][3] = a.w;
            win[dy][4] = bq.x; win[dy][5] = bq.y; win[dy][6] = bq.z; win[dy][7] = bq.w;
        }
        const float* Hm = &sH[m * 25];
#pragma unroll
        for (int du = 0; du < 5; du++)
#pragma unroll
            for (int dv = 0; dv < 5; dv++) {
                float h = Hm[du * 5 + dv];
#pragma unroll
                for (int ry = 0; ry < 2; ry++)
#pragma unroll
                    for (int rx = 0; rx < 4; rx++)
                        acc[ry][rx] = fmaf(h, win[ry + du][rx + dv], acc[ry][rx]);
            }
    }

    float rbv = __ldg(rb);
    float* op = out + (size_t)bz * HWp;
#pragma unroll
    for (int ry = 0; ry < 2; ry++) {
        int oy = gy0 + ty * 2 + ry;
        float4 o;
        o.x = acc[ry][0] + rbv; o.y = acc[ry][1] + rbv;
        o.z = acc[ry][2] + rbv; o.w = acc[ry][3] + rbv;
        *(float4*)&op[(size_t)oy * Wdim + gx0 + tx * 4] = o;
    }
}

// ---------------------------------------------------------------------------
// Kernel 2: border ring, ONE WARP PER PIXEL. Lanes 0..24 each handle one
// (du,dv) tap with closed-form cubic features; warp shfl reduce; lane 0
// stores. g_Hc is L2-resident (8KB).
// ---------------------------------------------------------------------------
__global__ void __launch_bounds__(256) border_kernel(const float* __restrict__ x,
                                                     float* __restrict__ out,
                                                     const float* __restrict__ rb)
{
    int gt   = blockIdx.x * 256 + threadIdx.x;
    int warp = gt >> 5;
    int lane = gt & 31;
    if (warp >= NBORD) return;

    int b = warp / PER_IMG, e = warp % PER_IMG;
    int i, j;
    if (e < Wdim)            { i = 0;        j = e; }
    else if (e < 2 * Wdim)   { i = Hdim - 1; j = e - Wdim; }
    else if (e < 2 * Wdim + (Hdim - 2)) { i = e - 2 * Wdim + 1; j = 0; }
    else                     { i = e - (2 * Wdim + (Hdim - 2)) + 1; j = Wdim - 1; }

    int ri = (i == 0) ? 0 : ((i == Hdim - 1) ? 2 : 1);
    int rj = (j == 0) ? 0 : ((j == Wdim - 1) ? 2 : 1);
    const float* Hc = g_Hc[ri * 3 + rj];

    float acc = 0.f;
    if (lane < 25) {
        int du = lane / 5, dv = lane - du * 5;
        int fy = i + du - 2, fx = j + dv - 2;
        float v = 0.f;
        if (fy >= 0 && fy < Hdim && fx >= 0 && fx < Wdim)
            v = __ldg(&x[(size_t)b * HWp + (size_t)fy * Wdim + fx]);

        float sig = 1.0f / (1.0f + __expf(-v));
        acc = (v * sig) * __ldg(&Hc[lane]);        // silu plane (m=0)

        float sc = (v + 2.2f) * 2.5f;
        float tf = floorf(sc);
        int   ti = (int)tf;
        if (ti >= 0 && ti <= 10) {
            float gt2 = tf * 0.4f - 2.2f;
            float u   = (v - gt2) * 2.5f;
            float u1  = 1.0f - u;
            float u2 = u * u, u12 = u1 * u1;
            const float c6 = 1.0f / 6.0f;
            float w[4];
            w[0] = u12 * u1 * c6;
            w[1] = (3.f*u2*u - 6.f*u2 + 4.f) * c6;
            w[2] = (-3.f*u2*u + 3.f*u2 + 3.f*u + 1.f) * c6;
            w[3] = u2 * u * c6;
            int m0 = ti - 3;
#pragma unroll
            for (int o = 0; o < 4; o++) {
                int mm = m0 + o;
                if (mm >= 0 && mm <= 7)
                    acc = fmaf(w[o], __ldg(&Hc[(mm + 1) * 25 + lane]), acc);
            }
        }
    }
#pragma unroll
    for (int off = 16; off >= 1; off >>= 1)
        acc += __shfl_xor_sync(0xffffffffu, acc, off);

    if (lane == 0)
        out[(size_t)b * HWp + (size_t)i * Wdim + j] = acc + __ldg(rb);
}

// ---------------------------------------------------------------------------
extern "C" void kernel_launch(void* const* d_in, const int* in_sizes, int n_in,
                              void* d_out, int out_size)
{
    const float* x  = (const float*)d_in[0];
    const float* bw = (const float*)d_in[1];
    const float* sw = (const float*)d_in[2];
    const float* ss = (const float*)d_in[3];
    const float* rw = (const float*)d_in[4];
    const float* rb = (const float*)d_in[5];
    float* out = (float*)d_out;

    dim3 grid(Wdim / 32, Hdim / 32, BATCH);
    main_kernel<<<grid, 128>>>(x, out, rb, bw, sw, ss, rw);
    int nwarps = NBORD;                      // one warp per border pixel
    int nthreads = nwarps * 32;
    border_kernel<<<(nthreads + 255) / 256, 256>>>(x, out, rb);
}